// round 1
// baseline (speedup 1.0000x reference)
#include <cuda_runtime.h>
#include <math.h>

// ---------------- problem dims ----------------
#define BB    2
#define TT    1024
#define NTOK  2048           // B*T
#define DD    1024
#define HQn   16
#define HKVn  4
#define KDn   64
#define VDn   64
#define Gn    4              // HQ/HKV
#define En    8
#define CAPn  1024           // floor(2048*0.5)
#define HIDn  2048

// ---------------- scratch (device globals; no allocation allowed) ----------------
__device__ float g_h   [NTOK*DD];            // rms1 output
__device__ float g_q   [NTOK*HQn*KDn];
__device__ float g_k   [NTOK*HKVn*KDn];
__device__ float g_v   [NTOK*HKVn*VDn];
__device__ float g_sc  [BB*HQn*TT*TT];       // scores/probs (134MB)
__device__ float g_attn[NTOK*DD];
__device__ float g_x1  [NTOK*DD];            // x + attn@wo
__device__ float g_h2  [NTOK*DD];            // rms2 output (= xf)
__device__ float g_grp [En*CAPn*DD];         // dispatched tokens
__device__ float g_t1  [En*CAPn*HIDn];       // w1 out, then hh (gelu) in-place
__device__ float g_t2  [En*CAPn*HIDn];       // w2 out
__device__ float g_eout[En*CAPn*DD];
__device__ int   g_assign[NTOK*2];
__device__ float g_gate  [NTOK*2];
__device__ int   g_slot  [NTOK*2];
__device__ int   g_keep  [NTOK*2];

// ---------------- rmsnorm ----------------
__global__ void rmsnorm_kernel(const float* __restrict__ x,
                               const float* __restrict__ scale,
                               float* __restrict__ out) {
    int row = blockIdx.x;
    const float* xr = x + (long long)row * DD;
    float* orow = out + (long long)row * DD;
    __shared__ float red[256];
    float s = 0.f;
    for (int d = threadIdx.x; d < DD; d += 256) { float v = xr[d]; s += v * v; }
    red[threadIdx.x] = s; __syncthreads();
    for (int o = 128; o > 0; o >>= 1) {
        if (threadIdx.x < o) red[threadIdx.x] += red[threadIdx.x + o];
        __syncthreads();
    }
    float inv = 1.0f / sqrtf(red[0] / (float)DD + 1e-6f);
    for (int d = threadIdx.x; d < DD; d += 256) orow[d] = xr[d] * inv * scale[d];
}

// ---------------- rope (in place) ----------------
__global__ void rope_kernel(float* __restrict__ p, int H, long long total) {
    long long i = (long long)blockIdx.x * 256 + threadIdx.x;
    if (i >= total) return;
    int j = (int)(i & 31);
    long long nh = i >> 5;
    int h = (int)(nh % H);
    long long n = nh / H;
    int t = (int)(n % TT);
    float* v = p + (n * H + h) * KDn;
    float theta = powf(10000.0f, -(2.0f * j) / 64.0f);
    float a = (float)t * theta;
    float c = cosf(a), s = sinf(a);
    float x1 = v[j], x2 = v[j + 32];
    v[j]      = x1 * c - x2 * s;
    v[j + 32] = x2 * c + x1 * s;
}

// ---------------- generic batched tiled SGEMM ----------------
// C = A*B (transB=0, B is KxN row-major) or C = A*B^T (transB=1, B is NxK row-major)
// per-z offsets: off = (z/zdiv)*so + ((z%zdiv)/div)*si
// epi: 0 plain, 1 v=v*scale; if(n>m) v=-1e9 (causal scores), 2 v += R[m*ldc+n]
__global__ void __launch_bounds__(256)
gemm_kernel(int M, int N, int K,
            const float* __restrict__ A, int lda, long long soA, long long siA, int divA,
            const float* __restrict__ B, int ldb, long long soB, long long siB, int divB,
            float* __restrict__ C, int ldc, long long soC, long long siC, int divC,
            int zdiv, int transB, int epi, float scale, const float* __restrict__ R) {
    int z = blockIdx.z;
    A += (long long)(z / zdiv) * soA + (long long)((z % zdiv) / divA) * siA;
    B += (long long)(z / zdiv) * soB + (long long)((z % zdiv) / divB) * siB;
    long long offC = (long long)(z / zdiv) * soC + (long long)((z % zdiv) / divC) * siC;
    C += offC;
    if (R) R += offC;

    __shared__ float As[8][128];
    __shared__ float Bs[8][128];

    int tid = threadIdx.x;
    int tx = tid & 15, ty = tid >> 4;
    int m0 = blockIdx.y * 128, n0 = blockIdx.x * 128;

    float acc[8][8];
    #pragma unroll
    for (int i = 0; i < 8; i++)
        #pragma unroll
        for (int j = 0; j < 8; j++) acc[i][j] = 0.f;

    // load index maps (M % 128 == 0 and K % 8 == 0 guaranteed by call sites)
    int a_r = tid >> 1;            // 0..127
    int a_c = (tid & 1) * 4;       // 0 or 4
    int b_k = tid >> 5;            // 0..7   (NN)
    int b_n = (tid & 31) * 4;      // 0..124 (NN)

    for (int k0 = 0; k0 < K; k0 += 8) {
        float4 av = *(const float4*)&A[(long long)(m0 + a_r) * lda + k0 + a_c];
        As[a_c + 0][a_r] = av.x;
        As[a_c + 1][a_r] = av.y;
        As[a_c + 2][a_r] = av.z;
        As[a_c + 3][a_r] = av.w;

        if (!transB) {
            int gn = n0 + b_n;
            float4 bv;
            if (gn + 3 < N) {
                bv = *(const float4*)&B[(long long)(k0 + b_k) * ldb + gn];
            } else {
                bv.x = (gn + 0 < N) ? B[(long long)(k0 + b_k) * ldb + gn + 0] : 0.f;
                bv.y = (gn + 1 < N) ? B[(long long)(k0 + b_k) * ldb + gn + 1] : 0.f;
                bv.z = (gn + 2 < N) ? B[(long long)(k0 + b_k) * ldb + gn + 2] : 0.f;
                bv.w = (gn + 3 < N) ? B[(long long)(k0 + b_k) * ldb + gn + 3] : 0.f;
            }
            *(float4*)&Bs[b_k][b_n] = bv;
        } else {
            int gn = n0 + a_r;
            float4 bv = make_float4(0.f, 0.f, 0.f, 0.f);
            if (gn < N) bv = *(const float4*)&B[(long long)gn * ldb + k0 + a_c];
            Bs[a_c + 0][a_r] = bv.x;
            Bs[a_c + 1][a_r] = bv.y;
            Bs[a_c + 2][a_r] = bv.z;
            Bs[a_c + 3][a_r] = bv.w;
        }
        __syncthreads();

        #pragma unroll
        for (int kk = 0; kk < 8; kk++) {
            float a[8], b[8];
            #pragma unroll
            for (int i = 0; i < 8; i++) a[i] = As[kk][ty * 8 + i];
            #pragma unroll
            for (int j = 0; j < 8; j++) b[j] = Bs[kk][tx * 8 + j];
            #pragma unroll
            for (int i = 0; i < 8; i++)
                #pragma unroll
                for (int j = 0; j < 8; j++)
                    acc[i][j] += a[i] * b[j];
        }
        __syncthreads();
    }

    #pragma unroll
    for (int i = 0; i < 8; i++) {
        int m = m0 + ty * 8 + i;
        #pragma unroll
        for (int j = 0; j < 8; j++) {
            int n = n0 + tx * 8 + j;
            if (n < N) {
                float v = acc[i][j];
                if (epi == 1) { v *= scale; if (n > m) v = -1e9f; }
                else if (epi == 2) { v += R[(long long)m * ldc + n]; }
                C[(long long)m * ldc + n] = v;
            }
        }
    }
}

// ---------------- row softmax over scores (in place) ----------------
__global__ void softmax_kernel() {
    long long row = blockIdx.x;
    float* p = g_sc + row * TT;
    __shared__ float red[256];
    int tid = threadIdx.x;
    float m = -3.4e38f;
    for (int j = tid; j < TT; j += 256) m = fmaxf(m, p[j]);
    red[tid] = m; __syncthreads();
    for (int o = 128; o > 0; o >>= 1) {
        if (tid < o) red[tid] = fmaxf(red[tid], red[tid + o]);
        __syncthreads();
    }
    float mx = red[0];
    __syncthreads();
    float s = 0.f;
    for (int j = tid; j < TT; j += 256) { float e = expf(p[j] - mx); p[j] = e; s += e; }
    red[tid] = s; __syncthreads();
    for (int o = 128; o > 0; o >>= 1) {
        if (tid < o) red[tid] += red[tid + o];
        __syncthreads();
    }
    float inv = 1.f / red[0];
    for (int j = tid; j < TT; j += 256) p[j] *= inv;
}

// ---------------- router (top-2 + softmax gate) ----------------
__global__ void router_kernel(const float* __restrict__ rw, const float* __restrict__ rb) {
    int t = blockIdx.x;
    const float* xr = g_h2 + (long long)t * DD;
    float part[En];
    #pragma unroll
    for (int e = 0; e < En; e++) part[e] = 0.f;
    for (int d = threadIdx.x; d < DD; d += 256) {
        float xv = xr[d];
        #pragma unroll
        for (int e = 0; e < En; e++) part[e] += xv * rw[d * En + e];
    }
    __shared__ float red[En][8];
    int lane = threadIdx.x & 31, warp = threadIdx.x >> 5;
    #pragma unroll
    for (int e = 0; e < En; e++) {
        float v = part[e];
        for (int o = 16; o > 0; o >>= 1) v += __shfl_down_sync(0xffffffffu, v, o);
        if (lane == 0) red[e][warp] = v;
    }
    __syncthreads();
    if (threadIdx.x == 0) {
        float lg[En];
        #pragma unroll
        for (int e = 0; e < En; e++) {
            float s = 0.f;
            for (int w = 0; w < 8; w++) s += red[e][w];
            lg[e] = s + rb[e];
        }
        int i0 = 0;
        for (int e = 1; e < En; e++) if (lg[e] > lg[i0]) i0 = e;
        int i1 = -1;
        for (int e = 0; e < En; e++) {
            if (e == i0) continue;
            if (i1 < 0 || lg[e] > lg[i1]) i1 = e;
        }
        float e1 = expf(lg[i1] - lg[i0]);
        float denom = 1.f + e1;
        g_assign[2 * t] = i0;     g_assign[2 * t + 1] = i1;
        g_gate[2 * t] = 1.f / denom; g_gate[2 * t + 1] = e1 / denom;
    }
}

// ---------------- serial capacity scan (replicates double-cumsum positions) ----------------
__global__ void scan_kernel() {
    int cnt0[En], cnt1[En];
    for (int e = 0; e < En; e++) { cnt0[e] = 0; cnt1[e] = 0; }
    for (int t = 0; t < NTOK; t++) {
        int a0 = g_assign[2 * t], a1 = g_assign[2 * t + 1];
        cnt0[a0]++; cnt1[a1]++;
        int p0 = cnt0[a0];
        int p1 = cnt0[a1] + cnt1[a1];
        g_slot[2 * t] = p0;     g_keep[2 * t] = (p0 < CAPn) ? 1 : 0;
        g_slot[2 * t + 1] = p1; g_keep[2 * t + 1] = (p1 < CAPn) ? 1 : 0;
    }
}

// ---------------- helpers ----------------
__global__ void zero_kernel(float* __restrict__ p, long long n) {
    long long i = (long long)blockIdx.x * 256 + threadIdx.x;
    if (i < n) p[i] = 0.f;
}

__global__ void scatter_kernel() {
    int i = blockIdx.x;              // 0..2*NTOK-1
    if (!g_keep[i]) return;
    int t = i >> 1;
    int e = g_assign[i], s = g_slot[i];
    float* dst = g_grp + ((long long)e * CAPn + s) * DD;
    const float* src = g_h2 + (long long)t * DD;
    for (int d = threadIdx.x; d < DD; d += 256) atomicAdd(&dst[d], src[d]);
}

__global__ void gelu_mul_kernel(long long n) {
    long long i = (long long)blockIdx.x * 256 + threadIdx.x;
    if (i >= n) return;
    float x = g_t2[i] * g_t1[i];
    float x3 = x * x * x;
    float inner = 0.7978845608028654f * (x + 0.044715f * x3);
    g_t1[i] = 0.5f * x * (1.0f + tanhf(inner));
}

__global__ void combine_kernel(float* __restrict__ out) {
    int t = blockIdx.x;
    float gte0 = g_gate[2 * t], gte1 = g_gate[2 * t + 1];
    const float* s0 = g_keep[2 * t]
        ? g_eout + ((long long)g_assign[2 * t] * CAPn + g_slot[2 * t]) * DD
        : g_h2 + (long long)t * DD;
    const float* s1 = g_keep[2 * t + 1]
        ? g_eout + ((long long)g_assign[2 * t + 1] * CAPn + g_slot[2 * t + 1]) * DD
        : g_h2 + (long long)t * DD;
    const float* xr = g_x1 + (long long)t * DD;
    float* orow = out + (long long)t * DD;
    for (int d = threadIdx.x; d < DD; d += 256)
        orow[d] = xr[d] + gte0 * s0[d] + gte1 * s1[d];
}

// ---------------- launch ----------------
extern "C" void kernel_launch(void* const* d_in, const int* in_sizes, int n_in,
                              void* d_out, int out_size) {
    const float* x   = (const float*)d_in[0];
    const float* wq  = (const float*)d_in[1];
    const float* wk  = (const float*)d_in[2];
    const float* wv  = (const float*)d_in[3];
    const float* wo  = (const float*)d_in[4];
    const float* rw  = (const float*)d_in[5];
    const float* rb  = (const float*)d_in[6];
    const float* w1  = (const float*)d_in[7];
    const float* w2  = (const float*)d_in[8];
    const float* w3  = (const float*)d_in[9];
    const float* ns1 = (const float*)d_in[10];
    const float* ns2 = (const float*)d_in[11];

    float *h, *q, *k, *v, *sc, *attn, *x1, *h2, *grp, *t1, *t2, *eout;
    cudaGetSymbolAddress((void**)&h, g_h);
    cudaGetSymbolAddress((void**)&q, g_q);
    cudaGetSymbolAddress((void**)&k, g_k);
    cudaGetSymbolAddress((void**)&v, g_v);
    cudaGetSymbolAddress((void**)&sc, g_sc);
    cudaGetSymbolAddress((void**)&attn, g_attn);
    cudaGetSymbolAddress((void**)&x1, g_x1);
    cudaGetSymbolAddress((void**)&h2, g_h2);
    cudaGetSymbolAddress((void**)&grp, g_grp);
    cudaGetSymbolAddress((void**)&t1, g_t1);
    cudaGetSymbolAddress((void**)&t2, g_t2);
    cudaGetSymbolAddress((void**)&eout, g_eout);

    auto launch_gemm = [&](int M, int N, int K,
                           const float* A, int lda, long long soA, long long siA, int divA,
                           const float* Bm, int ldb, long long soB, long long siB, int divB,
                           float* Cm, int ldc, long long soC, long long siC, int divC,
                           int Z, int zdiv, int transB, int epi, float scale, const float* R) {
        dim3 grid((N + 127) / 128, (M + 127) / 128, Z);
        gemm_kernel<<<grid, 256>>>(M, N, K,
                                   A, lda, soA, siA, divA,
                                   Bm, ldb, soB, siB, divB,
                                   Cm, ldc, soC, siC, divC,
                                   zdiv, transB, epi, scale, R);
    };

    // ---- attention ----
    rmsnorm_kernel<<<NTOK, 256>>>(x, ns1, h);
    launch_gemm(NTOK, 1024, 1024, h, 1024, 0, 0, 1, wq, 1024, 0, 0, 1,
                q, 1024, 0, 0, 1, 1, 1, 0, 0, 0.f, nullptr);
    launch_gemm(NTOK, 256, 1024, h, 1024, 0, 0, 1, wk, 256, 0, 0, 1,
                k, 256, 0, 0, 1, 1, 1, 0, 0, 0.f, nullptr);
    launch_gemm(NTOK, 256, 1024, h, 1024, 0, 0, 1, wv, 256, 0, 0, 1,
                v, 256, 0, 0, 1, 1, 1, 0, 0, 0.f, nullptr);
    {
        long long tq = (long long)NTOK * HQn * 32;
        rope_kernel<<<(unsigned)((tq + 255) / 256), 256>>>(q, HQn, tq);
        long long tk = (long long)NTOK * HKVn * 32;
        rope_kernel<<<(unsigned)((tk + 255) / 256), 256>>>(k, HKVn, tk);
    }
    // scores = q@k^T / 8, causal mask; z = b*16 + hq
    launch_gemm(TT, TT, KDn,
                q, 1024, (long long)TT * HQn * KDn, KDn, 1,
                k, 256, (long long)TT * HKVn * KDn, KDn, Gn,
                sc, TT, (long long)HQn * TT * TT, (long long)TT * TT, 1,
                BB * HQn, HQn, 1, 1, 0.125f, nullptr);
    softmax_kernel<<<BB * HQn * TT, 256>>>();
    // attn = probs @ v
    launch_gemm(TT, VDn, TT,
                sc, TT, (long long)HQn * TT * TT, (long long)TT * TT, 1,
                v, 256, (long long)TT * HKVn * VDn, VDn, Gn,
                attn, DD, (long long)TT * DD, VDn, 1,
                BB * HQn, HQn, 0, 0, 0.f, nullptr);
    // x1 = x + attn @ wo
    launch_gemm(NTOK, 1024, 1024, attn, 1024, 0, 0, 1, wo, 1024, 0, 0, 1,
                x1, 1024, 0, 0, 1, 1, 1, 0, 2, 0.f, x);

    // ---- MoE ----
    rmsnorm_kernel<<<NTOK, 256>>>(x1, ns2, h2);
    router_kernel<<<NTOK, 256>>>(rw, rb);
    scan_kernel<<<1, 1>>>();
    {
        long long n = (long long)En * CAPn * DD;
        zero_kernel<<<(unsigned)((n + 255) / 256), 256>>>(grp, n);
    }
    scatter_kernel<<<NTOK * 2, 256>>>();
    launch_gemm(CAPn, HIDn, DD,
                grp, DD, (long long)CAPn * DD, 0, 1,
                w1, HIDn, (long long)DD * HIDn, 0, 1,
                t1, HIDn, (long long)CAPn * HIDn, 0, 1,
                En, 1, 0, 0, 0.f, nullptr);
    launch_gemm(CAPn, HIDn, DD,
                grp, DD, (long long)CAPn * DD, 0, 1,
                w2, HIDn, (long long)DD * HIDn, 0, 1,
                t2, HIDn, (long long)CAPn * HIDn, 0, 1,
                En, 1, 0, 0, 0.f, nullptr);
    {
        long long n = (long long)En * CAPn * HIDn;
        gelu_mul_kernel<<<(unsigned)((n + 255) / 256), 256>>>(n);
    }
    launch_gemm(CAPn, DD, HIDn,
                t1, HIDn, (long long)CAPn * HIDn, 0, 1,
                w3, DD, (long long)HIDn * DD, 0, 1,
                eout, DD, (long long)CAPn * DD, 0, 1,
                En, 1, 0, 0, 0.f, nullptr);
    combine_kernel<<<NTOK, 256>>>((float*)d_out);
}

// round 2
// speedup vs baseline: 2.4298x; 2.4298x over previous
#include <cuda_runtime.h>
#include <cuda_bf16.h>
#include <math.h>
#include <stdint.h>

// ---------------- problem dims ----------------
#define BB    2
#define TT    1024
#define NTOK  2048
#define DD    1024
#define HQn   16
#define HKVn  4
#define KDn   64
#define VDn   64
#define Gn    4
#define En    8
#define CAPn  1024
#define HIDn  2048

// ---------------- fp32 scratch ----------------
__device__ float g_h   [NTOK*DD];
__device__ float g_q   [NTOK*HQn*KDn];
__device__ float g_k   [NTOK*HKVn*KDn];
__device__ float g_v   [NTOK*HKVn*VDn];
__device__ float g_sc  [BB*HQn*TT*TT];
__device__ float g_attn[NTOK*DD];
__device__ float g_x1  [NTOK*DD];
__device__ float g_h2  [NTOK*DD];
__device__ float g_grp [En*CAPn*DD];
__device__ float g_t1  [En*CAPn*HIDn];
__device__ float g_t2  [En*CAPn*HIDn];
__device__ float g_eout[En*CAPn*DD];
__device__ int   g_assign[NTOK*2];
__device__ float g_gate  [NTOK*2];
__device__ int   g_slot  [NTOK*2];
__device__ int   g_keep  [NTOK*2];

// ---------------- bf16 hi/lo scratch ----------------
#define SZ_H   (NTOK*DD)
#define SZ_Q   (NTOK*HQn*KDn)
#define SZ_K   (NTOK*HKVn*KDn)
#define SZ_VT  (BB*HKVn*VDn*TT)
#define SZ_P   (BB*HQn*TT*TT)
#define SZ_ATT (NTOK*DD)
#define SZ_GRP (En*CAPn*DD)
#define SZ_T1  (En*CAPn*HIDn)
#define SZ_WQT (DD*DD)
#define SZ_WKT (256*DD)
#define SZ_WOT (DD*DD)
#define SZ_W1T (En*HIDn*DD)
#define SZ_W3T (En*DD*HIDn)

__device__ __nv_bfloat16 b_h   [2*SZ_H];
__device__ __nv_bfloat16 b_q   [2*SZ_Q];
__device__ __nv_bfloat16 b_k   [2*SZ_K];
__device__ __nv_bfloat16 b_vt  [2*SZ_VT];
__device__ __nv_bfloat16 b_p   [2*SZ_P];
__device__ __nv_bfloat16 b_attn[2*SZ_ATT];
__device__ __nv_bfloat16 b_grp [2*SZ_GRP];
__device__ __nv_bfloat16 b_t1  [2*SZ_T1];
__device__ __nv_bfloat16 b_wqT [2*SZ_WQT];
__device__ __nv_bfloat16 b_wkT [2*SZ_WKT];
__device__ __nv_bfloat16 b_wvT [2*SZ_WKT];
__device__ __nv_bfloat16 b_woT [2*SZ_WOT];
__device__ __nv_bfloat16 b_w1T [2*SZ_W1T];
__device__ __nv_bfloat16 b_w2T [2*SZ_W1T];
__device__ __nv_bfloat16 b_w3T [2*SZ_W3T];

// ---------------- small kernels ----------------
__global__ void rmsnorm_kernel(const float* __restrict__ x,
                               const float* __restrict__ scale,
                               float* __restrict__ out) {
    int row = blockIdx.x;
    const float* xr = x + (long long)row * DD;
    float* orow = out + (long long)row * DD;
    __shared__ float red[256];
    float s = 0.f;
    for (int d = threadIdx.x; d < DD; d += 256) { float v = xr[d]; s += v * v; }
    red[threadIdx.x] = s; __syncthreads();
    for (int o = 128; o > 0; o >>= 1) {
        if (threadIdx.x < o) red[threadIdx.x] += red[threadIdx.x + o];
        __syncthreads();
    }
    float inv = 1.0f / sqrtf(red[0] / (float)DD + 1e-6f);
    for (int d = threadIdx.x; d < DD; d += 256) orow[d] = xr[d] * inv * scale[d];
}

__global__ void rope_kernel(float* __restrict__ p, int H, long long total) {
    long long i = (long long)blockIdx.x * 256 + threadIdx.x;
    if (i >= total) return;
    int j = (int)(i & 31);
    long long nh = i >> 5;
    int h = (int)(nh % H);
    long long n = nh / H;
    int t = (int)(n % TT);
    float* v = p + (n * H + h) * KDn;
    float theta = powf(10000.0f, -(2.0f * j) / 64.0f);
    float a = (float)t * theta;
    float c = cosf(a), s = sinf(a);
    float x1 = v[j], x2 = v[j + 32];
    v[j]      = x1 * c - x2 * s;
    v[j + 32] = x2 * c + x1 * s;
}

__global__ void softmax_kernel() {
    long long row = blockIdx.x;
    float* p = g_sc + row * TT;
    __shared__ float red[256];
    int tid = threadIdx.x;
    float m = -3.4e38f;
    for (int j = tid; j < TT; j += 256) m = fmaxf(m, p[j]);
    red[tid] = m; __syncthreads();
    for (int o = 128; o > 0; o >>= 1) {
        if (tid < o) red[tid] = fmaxf(red[tid], red[tid + o]);
        __syncthreads();
    }
    float mx = red[0];
    __syncthreads();
    float s = 0.f;
    for (int j = tid; j < TT; j += 256) { float e = expf(p[j] - mx); p[j] = e; s += e; }
    red[tid] = s; __syncthreads();
    for (int o = 128; o > 0; o >>= 1) {
        if (tid < o) red[tid] += red[tid + o];
        __syncthreads();
    }
    float inv = 1.f / red[0];
    for (int j = tid; j < TT; j += 256) p[j] *= inv;
}

__global__ void router_kernel(const float* __restrict__ rw, const float* __restrict__ rb) {
    int t = blockIdx.x;
    const float* xr = g_h2 + (long long)t * DD;
    float part[En];
    #pragma unroll
    for (int e = 0; e < En; e++) part[e] = 0.f;
    for (int d = threadIdx.x; d < DD; d += 256) {
        float xv = xr[d];
        #pragma unroll
        for (int e = 0; e < En; e++) part[e] += xv * rw[d * En + e];
    }
    __shared__ float red[En][8];
    int lane = threadIdx.x & 31, warp = threadIdx.x >> 5;
    #pragma unroll
    for (int e = 0; e < En; e++) {
        float v = part[e];
        for (int o = 16; o > 0; o >>= 1) v += __shfl_down_sync(0xffffffffu, v, o);
        if (lane == 0) red[e][warp] = v;
    }
    __syncthreads();
    if (threadIdx.x == 0) {
        float lg[En];
        #pragma unroll
        for (int e = 0; e < En; e++) {
            float s = 0.f;
            for (int w = 0; w < 8; w++) s += red[e][w];
            lg[e] = s + rb[e];
        }
        int i0 = 0;
        for (int e = 1; e < En; e++) if (lg[e] > lg[i0]) i0 = e;
        int i1 = -1;
        for (int e = 0; e < En; e++) {
            if (e == i0) continue;
            if (i1 < 0 || lg[e] > lg[i1]) i1 = e;
        }
        float e1 = expf(lg[i1] - lg[i0]);
        float denom = 1.f + e1;
        g_assign[2 * t] = i0;     g_assign[2 * t + 1] = i1;
        g_gate[2 * t] = 1.f / denom; g_gate[2 * t + 1] = e1 / denom;
    }
}

__global__ void scan_kernel() {
    int cnt0[En], cnt1[En];
    for (int e = 0; e < En; e++) { cnt0[e] = 0; cnt1[e] = 0; }
    for (int t = 0; t < NTOK; t++) {
        int a0 = g_assign[2 * t], a1 = g_assign[2 * t + 1];
        cnt0[a0]++; cnt1[a1]++;
        int p0 = cnt0[a0];
        int p1 = cnt0[a1] + cnt1[a1];
        g_slot[2 * t] = p0;     g_keep[2 * t] = (p0 < CAPn) ? 1 : 0;
        g_slot[2 * t + 1] = p1; g_keep[2 * t + 1] = (p1 < CAPn) ? 1 : 0;
    }
}

__global__ void zero_kernel(float* __restrict__ p, long long n) {
    long long i = (long long)blockIdx.x * 256 + threadIdx.x;
    if (i < n) p[i] = 0.f;
}

__global__ void scatter_kernel() {
    int i = blockIdx.x;
    if (!g_keep[i]) return;
    int t = i >> 1;
    int e = g_assign[i], s = g_slot[i];
    float* dst = g_grp + ((long long)e * CAPn + s) * DD;
    const float* src = g_h2 + (long long)t * DD;
    for (int d = threadIdx.x; d < DD; d += 256) atomicAdd(&dst[d], src[d]);
}

__global__ void gelu_mul_kernel(long long n) {
    long long i = (long long)blockIdx.x * 256 + threadIdx.x;
    if (i >= n) return;
    float x = g_t2[i] * g_t1[i];
    float x3 = x * x * x;
    float inner = 0.7978845608028654f * (x + 0.044715f * x3);
    g_t1[i] = 0.5f * x * (1.0f + tanhf(inner));
}

__global__ void combine_kernel(float* __restrict__ out) {
    int t = blockIdx.x;
    float gte0 = g_gate[2 * t], gte1 = g_gate[2 * t + 1];
    const float* s0 = g_keep[2 * t]
        ? g_eout + ((long long)g_assign[2 * t] * CAPn + g_slot[2 * t]) * DD
        : g_h2 + (long long)t * DD;
    const float* s1 = g_keep[2 * t + 1]
        ? g_eout + ((long long)g_assign[2 * t + 1] * CAPn + g_slot[2 * t + 1]) * DD
        : g_h2 + (long long)t * DD;
    const float* xr = g_x1 + (long long)t * DD;
    float* orow = out + (long long)t * DD;
    for (int d = threadIdx.x; d < DD; d += 256)
        orow[d] = xr[d] + gte0 * s0[d] + gte1 * s1[d];
}

// ---------------- fp32 -> bf16 hi/lo conversion ----------------
__global__ void conv_kernel(const float* __restrict__ src, __nv_bfloat16* __restrict__ hi,
                            __nv_bfloat16* __restrict__ lo, long long n) {
    long long i = (long long)blockIdx.x * 256 + threadIdx.x;
    if (i >= n) return;
    float v = src[i];
    __nv_bfloat16 h = __float2bfloat16(v);
    hi[i] = h; lo[i] = __float2bfloat16(v - __bfloat162float(h));
}

// batched transpose + convert: dst[z][c][r] = src[(z/zdiv)*so + (z%zdiv)*si + r*lds + c]
__global__ void tconv_kernel(const float* __restrict__ src, __nv_bfloat16* __restrict__ hi,
                             __nv_bfloat16* __restrict__ lo, int R, int C, int lds,
                             long long so, long long si, int zdiv) {
    int z = blockIdx.z;
    src += (long long)(z / zdiv) * so + (long long)(z % zdiv) * si;
    long long d = (long long)z * R * C;
    hi += d; lo += d;
    __shared__ float t[32][33];
    int c0 = blockIdx.x * 32, r0 = blockIdx.y * 32;
    for (int i = threadIdx.y; i < 32; i += 8) {
        int r = r0 + i, c = c0 + threadIdx.x;
        if (r < R && c < C) t[i][threadIdx.x] = src[(long long)r * lds + c];
    }
    __syncthreads();
    for (int i = threadIdx.y; i < 32; i += 8) {
        int c = c0 + i, r = r0 + threadIdx.x;
        if (r < R && c < C) {
            float v = t[threadIdx.x][i];
            __nv_bfloat16 hh = __float2bfloat16(v);
            hi[(long long)c * R + r] = hh;
            lo[(long long)c * R + r] = __float2bfloat16(v - __bfloat162float(hh));
        }
    }
}

// ---------------- bf16 split-precision tensor-core GEMM (NT) ----------------
// C(MxN) = (Ah+Al)(MxK, row-major) * (Bh+Bl)^T (B stored N x K row-major)
// dropped Al*Bl term (negligible). fp32 accumulate.
#define TILEE (128*16)

__device__ __forceinline__ int swz(int row, int k) {
    return row * 16 + ((((k >> 3) ^ (row >> 2)) & 1) << 3) + (k & 7);
}

#define LDSM4(r0,r1,r2,r3,a) \
  asm volatile("ldmatrix.sync.aligned.m8n8.x4.shared.b16 {%0,%1,%2,%3}, [%4];" \
    : "=r"(r0), "=r"(r1), "=r"(r2), "=r"(r3) : "r"(a))

#define MMA16816(d, a, b) \
  asm volatile("mma.sync.aligned.m16n8k16.row.col.f32.bf16.bf16.f32 " \
    "{%0,%1,%2,%3}, {%4,%5,%6,%7}, {%8,%9}, {%0,%1,%2,%3};" \
    : "+f"(d[0]), "+f"(d[1]), "+f"(d[2]), "+f"(d[3]) \
    : "r"(a[0]), "r"(a[1]), "r"(a[2]), "r"(a[3]), "r"(b[0]), "r"(b[1]))

__global__ void __launch_bounds__(256)
bgemm_kernel(int M, int N, int K,
             const __nv_bfloat16* __restrict__ Ah, const __nv_bfloat16* __restrict__ Al,
             int lda, long long soA, long long siA, int divA,
             const __nv_bfloat16* __restrict__ Bh, const __nv_bfloat16* __restrict__ Bl,
             int ldb, long long soB, long long siB, int divB,
             float* __restrict__ C, int ldc, long long soC, long long siC, int divC,
             int zdiv, int epi, float scale, const float* __restrict__ Rz, int causalA) {
    int z = blockIdx.z;
    long long offA = (long long)(z / zdiv) * soA + (long long)((z % zdiv) / divA) * siA;
    long long offB = (long long)(z / zdiv) * soB + (long long)((z % zdiv) / divB) * siB;
    long long offC = (long long)(z / zdiv) * soC + (long long)((z % zdiv) / divC) * siC;
    Ah += offA; Al += offA; Bh += offB; Bl += offB; C += offC;
    const float* Rp = Rz ? (Rz + offC) : (const float*)0;

    int m0 = blockIdx.y * 128, n0 = blockIdx.x * 128;
    int tid = threadIdx.x;

    // fully-masked causal block: write -1e9, skip all math
    if (epi == 1 && n0 >= m0 + 128) {
        for (int idx = tid; idx < 128 * 128; idx += 256) {
            int r = idx >> 7, c = idx & 127;
            if (n0 + c < N) C[(long long)(m0 + r) * ldc + n0 + c] = -1e9f;
        }
        return;
    }

    __shared__ __nv_bfloat16 sm[2][4][TILEE];
    uint32_t sbase = (uint32_t)__cvta_generic_to_shared(&sm[0][0][0]);

    int lr = tid >> 1, lc = tid & 1;
    const __nv_bfloat16* gAh = Ah + (long long)(m0 + lr) * lda + lc * 8;
    const __nv_bfloat16* gAl = Al + (long long)(m0 + lr) * lda + lc * 8;
    int brow = n0 + lr;
    int bvalid = (brow < N) ? 1 : 0;
    const __nv_bfloat16* gBh = Bh + (long long)(bvalid ? brow : 0) * ldb + lc * 8;
    const __nv_bfloat16* gBl = Bl + (long long)(bvalid ? brow : 0) * ldb + lc * 8;
    unsigned bsz = bvalid ? 16u : 0u;
    uint32_t soff = (uint32_t)swz(lr, lc * 8) * 2;

    int KT = K / 16;
    if (causalA) { int kt2 = (m0 + 128) / 16; if (kt2 < KT) KT = kt2; }

    auto prefetch = [&](int kt, int st) {
        long long ko = (long long)kt * 16;
        uint32_t b0 = sbase + (uint32_t)(st * 4 * TILEE * 2);
        asm volatile("cp.async.cg.shared.global [%0], [%1], 16;"
                     :: "r"(b0 + soff), "l"(gAh + ko));
        asm volatile("cp.async.cg.shared.global [%0], [%1], 16;"
                     :: "r"(b0 + (uint32_t)(TILEE * 2) + soff), "l"(gAl + ko));
        asm volatile("cp.async.cg.shared.global [%0], [%1], 16, %2;"
                     :: "r"(b0 + (uint32_t)(2 * TILEE * 2) + soff), "l"(gBh + ko), "r"(bsz));
        asm volatile("cp.async.cg.shared.global [%0], [%1], 16, %2;"
                     :: "r"(b0 + (uint32_t)(3 * TILEE * 2) + soff), "l"(gBl + ko), "r"(bsz));
    };

    float acc[4][4][4];
    #pragma unroll
    for (int i = 0; i < 4; i++)
        #pragma unroll
        for (int j = 0; j < 4; j++)
            #pragma unroll
            for (int e = 0; e < 4; e++) acc[i][j][e] = 0.f;

    int lane = tid & 31, wid = tid >> 5;
    int wm = wid & 1, wn = wid >> 1;
    int arow = wm * 64 + (lane & 15);
    int ak = (lane >> 4) * 8;
    int brow2 = wn * 32 + (lane & 7) + ((lane & 16) ? 8 : 0);
    int bk = (lane & 8) ? 8 : 0;

    prefetch(0, 0);
    asm volatile("cp.async.commit_group;");

    for (int kt = 0; kt < KT; kt++) {
        int st = kt & 1;
        if (kt + 1 < KT) {
            prefetch(kt + 1, st ^ 1);
            asm volatile("cp.async.commit_group;");
            asm volatile("cp.async.wait_group 1;");
        } else {
            asm volatile("cp.async.wait_group 0;");
        }
        __syncthreads();

        uint32_t base = sbase + (uint32_t)(st * 4 * TILEE * 2);
        uint32_t fAh[4][4], fAl[4][4], fBh[4][2], fBl[4][2];
        #pragma unroll
        for (int mi = 0; mi < 4; mi++) {
            uint32_t ao = base + (uint32_t)swz(arow + mi * 16, ak) * 2;
            LDSM4(fAh[mi][0], fAh[mi][1], fAh[mi][2], fAh[mi][3], ao);
            LDSM4(fAl[mi][0], fAl[mi][1], fAl[mi][2], fAl[mi][3], ao + (uint32_t)(TILEE * 2));
        }
        #pragma unroll
        for (int nj = 0; nj < 2; nj++) {
            uint32_t bo = base + (uint32_t)(2 * TILEE * 2) + (uint32_t)swz(brow2 + nj * 16, bk) * 2;
            uint32_t r0, r1, r2, r3;
            LDSM4(r0, r1, r2, r3, bo);
            fBh[nj * 2][0] = r0; fBh[nj * 2][1] = r1;
            fBh[nj * 2 + 1][0] = r2; fBh[nj * 2 + 1][1] = r3;
            LDSM4(r0, r1, r2, r3, bo + (uint32_t)(TILEE * 2));
            fBl[nj * 2][0] = r0; fBl[nj * 2][1] = r1;
            fBl[nj * 2 + 1][0] = r2; fBl[nj * 2 + 1][1] = r3;
        }
        #pragma unroll
        for (int mi = 0; mi < 4; mi++)
            #pragma unroll
            for (int ni = 0; ni < 4; ni++) {
                MMA16816(acc[mi][ni], fAh[mi], fBh[ni]);
                MMA16816(acc[mi][ni], fAh[mi], fBl[ni]);
                MMA16816(acc[mi][ni], fAl[mi], fBh[ni]);
            }
        __syncthreads();
    }

    int r4 = lane >> 2, c2 = (lane & 3) * 2;
    #pragma unroll
    for (int mi = 0; mi < 4; mi++)
        #pragma unroll
        for (int ni = 0; ni < 4; ni++) {
            int row = m0 + wm * 64 + mi * 16 + r4;
            int col = n0 + wn * 32 + ni * 8 + c2;
            #pragma unroll
            for (int e = 0; e < 4; e++) {
                int rr = row + (e >> 1) * 8;
                int cc = col + (e & 1);
                if (cc < N) {
                    float v = acc[mi][ni][e];
                    if (epi == 1) { v *= scale; if (cc > rr) v = -1e9f; }
                    else if (epi == 2) v += Rp[(long long)rr * ldc + cc];
                    C[(long long)rr * ldc + cc] = v;
                }
            }
        }
}

// ---------------- launch ----------------
extern "C" void kernel_launch(void* const* d_in, const int* in_sizes, int n_in,
                              void* d_out, int out_size) {
    const float* x   = (const float*)d_in[0];
    const float* wq  = (const float*)d_in[1];
    const float* wk  = (const float*)d_in[2];
    const float* wv  = (const float*)d_in[3];
    const float* wo  = (const float*)d_in[4];
    const float* rw  = (const float*)d_in[5];
    const float* rb  = (const float*)d_in[6];
    const float* w1  = (const float*)d_in[7];
    const float* w2  = (const float*)d_in[8];
    const float* w3  = (const float*)d_in[9];
    const float* ns1 = (const float*)d_in[10];
    const float* ns2 = (const float*)d_in[11];

    float *h, *q, *k, *v, *sc, *attn, *x1, *h2, *grp, *t1, *t2, *eout;
    cudaGetSymbolAddress((void**)&h, g_h);
    cudaGetSymbolAddress((void**)&q, g_q);
    cudaGetSymbolAddress((void**)&k, g_k);
    cudaGetSymbolAddress((void**)&v, g_v);
    cudaGetSymbolAddress((void**)&sc, g_sc);
    cudaGetSymbolAddress((void**)&attn, g_attn);
    cudaGetSymbolAddress((void**)&x1, g_x1);
    cudaGetSymbolAddress((void**)&h2, g_h2);
    cudaGetSymbolAddress((void**)&grp, g_grp);
    cudaGetSymbolAddress((void**)&t1, g_t1);
    cudaGetSymbolAddress((void**)&t2, g_t2);
    cudaGetSymbolAddress((void**)&eout, g_eout);

    __nv_bfloat16 *bh, *bq, *bk, *bvt, *bp, *batt, *bgrp, *bt1;
    __nv_bfloat16 *wqT, *wkT, *wvT, *woT, *w1T, *w2T, *w3T;
    cudaGetSymbolAddress((void**)&bh, b_h);
    cudaGetSymbolAddress((void**)&bq, b_q);
    cudaGetSymbolAddress((void**)&bk, b_k);
    cudaGetSymbolAddress((void**)&bvt, b_vt);
    cudaGetSymbolAddress((void**)&bp, b_p);
    cudaGetSymbolAddress((void**)&batt, b_attn);
    cudaGetSymbolAddress((void**)&bgrp, b_grp);
    cudaGetSymbolAddress((void**)&bt1, b_t1);
    cudaGetSymbolAddress((void**)&wqT, b_wqT);
    cudaGetSymbolAddress((void**)&wkT, b_wkT);
    cudaGetSymbolAddress((void**)&wvT, b_wvT);
    cudaGetSymbolAddress((void**)&woT, b_woT);
    cudaGetSymbolAddress((void**)&w1T, b_w1T);
    cudaGetSymbolAddress((void**)&w2T, b_w2T);
    cudaGetSymbolAddress((void**)&w3T, b_w3T);

    auto conv = [&](const float* s, __nv_bfloat16* d, long long size) {
        conv_kernel<<<(unsigned)((size + 255) / 256), 256>>>(s, d, d + size, size);
    };
    auto tconv = [&](const float* s, __nv_bfloat16* d, long long size,
                     int R, int C, int lds, long long so, long long si, int zdiv, int Z) {
        dim3 grid((C + 31) / 32, (R + 31) / 32, Z);
        tconv_kernel<<<grid, dim3(32, 8)>>>(s, d, d + size, R, C, lds, so, si, zdiv);
    };
    auto bgemm = [&](int M, int N, int K,
                     const __nv_bfloat16* A, long long szA, int lda, long long soA, long long siA, int divA,
                     const __nv_bfloat16* B, long long szB, int ldb, long long soB, long long siB, int divB,
                     float* C, int ldc, long long soC, long long siC, int divC,
                     int Z, int zdiv, int epi, float scale, const float* R, int causalA) {
        dim3 grid((N + 127) / 128, M / 128, Z);
        bgemm_kernel<<<grid, 256>>>(M, N, K,
                                    A, A + szA, lda, soA, siA, divA,
                                    B, B + szB, ldb, soB, siB, divB,
                                    C, ldc, soC, siC, divC,
                                    zdiv, epi, scale, R, causalA);
    };

    // weight transposes + conversions (NT layout: N x K)
    tconv(wq, wqT, SZ_WQT, 1024, 1024, 1024, 0, 0, 1, 1);
    tconv(wk, wkT, SZ_WKT, 1024, 256, 256, 0, 0, 1, 1);
    tconv(wv, wvT, SZ_WKT, 1024, 256, 256, 0, 0, 1, 1);
    tconv(wo, woT, SZ_WOT, 1024, 1024, 1024, 0, 0, 1, 1);
    tconv(w1, w1T, SZ_W1T, 1024, 2048, 2048, (long long)DD * HIDn, 0, 1, En);
    tconv(w2, w2T, SZ_W1T, 1024, 2048, 2048, (long long)DD * HIDn, 0, 1, En);
    tconv(w3, w3T, SZ_W3T, 2048, 1024, 1024, (long long)HIDn * DD, 0, 1, En);

    // ---- attention ----
    rmsnorm_kernel<<<NTOK, 256>>>(x, ns1, h);
    conv(h, bh, SZ_H);
    bgemm(NTOK, 1024, 1024, bh, SZ_H, 1024, 0, 0, 1, wqT, SZ_WQT, 1024, 0, 0, 1,
          q, 1024, 0, 0, 1, 1, 1, 0, 0.f, nullptr, 0);
    bgemm(NTOK, 256, 1024, bh, SZ_H, 1024, 0, 0, 1, wkT, SZ_WKT, 1024, 0, 0, 1,
          k, 256, 0, 0, 1, 1, 1, 0, 0.f, nullptr, 0);
    bgemm(NTOK, 256, 1024, bh, SZ_H, 1024, 0, 0, 1, wvT, SZ_WKT, 1024, 0, 0, 1,
          v, 256, 0, 0, 1, 1, 1, 0, 0.f, nullptr, 0);
    {
        long long tq = (long long)NTOK * HQn * 32;
        rope_kernel<<<(unsigned)((tq + 255) / 256), 256>>>(q, HQn, tq);
        long long tk = (long long)NTOK * HKVn * 32;
        rope_kernel<<<(unsigned)((tk + 255) / 256), 256>>>(k, HKVn, tk);
    }
    conv(q, bq, SZ_Q);
    conv(k, bk, SZ_K);
    // v -> transposed per (b,h): [VD][T]
    tconv(v, bvt, SZ_VT, TT, VDn, HKVn * VDn, (long long)TT * HKVn * VDn, VDn, HKVn, BB * HKVn);

    // scores = q@k^T / 8, causal
    bgemm(TT, TT, KDn,
          bq, SZ_Q, 1024, (long long)TT * HQn * KDn, KDn, 1,
          bk, SZ_K, 256, (long long)TT * HKVn * KDn, KDn, Gn,
          sc, TT, (long long)HQn * TT * TT, (long long)TT * TT, 1,
          BB * HQn, HQn, 1, 0.125f, nullptr, 0);
    softmax_kernel<<<BB * HQn * TT, 256>>>();
    conv(sc, bp, SZ_P);
    // attn = probs @ v   (B = v^T, N=64; causal A skips zero K tiles)
    bgemm(TT, VDn, TT,
          bp, SZ_P, TT, (long long)HQn * TT * TT, (long long)TT * TT, 1,
          bvt, SZ_VT, TT, (long long)HKVn * VDn * TT, (long long)VDn * TT, Gn,
          attn, DD, (long long)TT * DD, VDn, 1,
          BB * HQn, HQn, 0, 0.f, nullptr, 1);
    conv(attn, batt, SZ_ATT);
    // x1 = x + attn @ wo
    bgemm(NTOK, 1024, 1024, batt, SZ_ATT, 1024, 0, 0, 1, woT, SZ_WOT, 1024, 0, 0, 1,
          x1, 1024, 0, 0, 1, 1, 1, 2, 0.f, x, 0);

    // ---- MoE ----
    rmsnorm_kernel<<<NTOK, 256>>>(x1, ns2, h2);
    router_kernel<<<NTOK, 256>>>(rw, rb);
    scan_kernel<<<1, 1>>>();
    {
        long long n = (long long)En * CAPn * DD;
        zero_kernel<<<(unsigned)((n + 255) / 256), 256>>>(grp, n);
    }
    scatter_kernel<<<NTOK * 2, 256>>>();
    conv(grp, bgrp, SZ_GRP);
    bgemm(CAPn, HIDn, DD,
          bgrp, SZ_GRP, 1024, (long long)CAPn * DD, 0, 1,
          w1T, SZ_W1T, 1024, (long long)HIDn * DD, 0, 1,
          t1, HIDn, (long long)CAPn * HIDn, 0, 1,
          En, 1, 0, 0.f, nullptr, 0);
    bgemm(CAPn, HIDn, DD,
          bgrp, SZ_GRP, 1024, (long long)CAPn * DD, 0, 1,
          w2T, SZ_W1T, 1024, (long long)HIDn * DD, 0, 1,
          t2, HIDn, (long long)CAPn * HIDn, 0, 1,
          En, 1, 0, 0.f, nullptr, 0);
    {
        long long n = (long long)En * CAPn * HIDn;
        gelu_mul_kernel<<<(unsigned)((n + 255) / 256), 256>>>(n);
    }
    conv(t1, bt1, SZ_T1);
    bgemm(CAPn, DD, HIDn,
          bt1, SZ_T1, HIDn, (long long)CAPn * HIDn, 0, 1,
          w3T, SZ_W3T, 2048, (long long)DD * HIDn, 0, 1,
          eout, DD, (long long)CAPn * DD, 0, 1,
          En, 1, 0, 0.f, nullptr, 0);
    combine_kernel<<<NTOK, 256>>>((float*)d_out);
}

// round 3
// speedup vs baseline: 2.8370x; 1.1676x over previous
#include <cuda_runtime.h>
#include <cuda_bf16.h>
#include <math.h>
#include <stdint.h>

// ---------------- problem dims ----------------
#define BB    2
#define TT    1024
#define NTOK  2048
#define DD    1024
#define HQn   16
#define HKVn  4
#define KDn   64
#define VDn   64
#define Gn    4
#define En    8
#define CAPn  1024
#define HIDn  2048

// ---------------- fp32 scratch ----------------
__device__ float g_q   [NTOK*HQn*KDn];
__device__ float g_k   [NTOK*HKVn*KDn];
__device__ float g_v   [NTOK*HKVn*VDn];
__device__ float g_x1  [NTOK*DD];
__device__ float g_h2  [NTOK*DD];
__device__ float g_grp [En*CAPn*DD];
__device__ float g_t1  [En*CAPn*HIDn];
__device__ float g_t2  [En*CAPn*HIDn];
__device__ float g_eout[En*CAPn*DD];
__device__ int   g_assign[NTOK*2];
__device__ float g_gate  [NTOK*2];
__device__ int   g_slot  [NTOK*2];
__device__ int   g_keep  [NTOK*2];

// ---------------- bf16 hi/lo scratch ----------------
#define SZ_H   (NTOK*DD)
#define SZ_Q   (NTOK*HQn*KDn)
#define SZ_K   (NTOK*HKVn*KDn)
#define SZ_VT  (BB*HKVn*VDn*TT)
#define SZ_ATT (NTOK*DD)
#define SZ_GRP (En*CAPn*DD)
#define SZ_T1  (En*CAPn*HIDn)
#define SZ_WQT (DD*DD)
#define SZ_WKT (256*DD)
#define SZ_WOT (DD*DD)
#define SZ_W1T (En*HIDn*DD)
#define SZ_W3T (En*DD*HIDn)

__device__ __nv_bfloat16 b_h   [2*SZ_H];
__device__ __nv_bfloat16 b_q   [2*SZ_Q];
__device__ __nv_bfloat16 b_k   [2*SZ_K];
__device__ __nv_bfloat16 b_vt  [2*SZ_VT];
__device__ __nv_bfloat16 b_attn[2*SZ_ATT];
__device__ __nv_bfloat16 b_grp [2*SZ_GRP];
__device__ __nv_bfloat16 b_t1  [2*SZ_T1];
__device__ __nv_bfloat16 b_wqT [2*SZ_WQT];
__device__ __nv_bfloat16 b_wkT [2*SZ_WKT];
__device__ __nv_bfloat16 b_wvT [2*SZ_WKT];
__device__ __nv_bfloat16 b_woT [2*SZ_WOT];
__device__ __nv_bfloat16 b_w1T [2*SZ_W1T];
__device__ __nv_bfloat16 b_w2T [2*SZ_W1T];
__device__ __nv_bfloat16 b_w3T [2*SZ_W3T];

// ---------------- helpers ----------------
__device__ __forceinline__ uint32_t pack2(float a, float b) {
    __nv_bfloat162 t = __floats2bfloat162_rn(a, b);
    return *reinterpret_cast<uint32_t*>(&t);
}
__device__ __forceinline__ float lopart(float x) {
    return x - __bfloat162float(__float2bfloat16(x));
}
__device__ __forceinline__ int swz(int row, int k) {
    return row * 16 + ((((k >> 3) ^ (row >> 2)) & 1) << 3) + (k & 7);
}

#define LDSM4(r0,r1,r2,r3,a) \
  asm volatile("ldmatrix.sync.aligned.m8n8.x4.shared.b16 {%0,%1,%2,%3}, [%4];" \
    : "=r"(r0), "=r"(r1), "=r"(r2), "=r"(r3) : "r"(a))

#define MMA16816(d, a, b) \
  asm volatile("mma.sync.aligned.m16n8k16.row.col.f32.bf16.bf16.f32 " \
    "{%0,%1,%2,%3}, {%4,%5,%6,%7}, {%8,%9}, {%0,%1,%2,%3};" \
    : "+f"(d[0]), "+f"(d[1]), "+f"(d[2]), "+f"(d[3]) \
    : "r"(a[0]), "r"(a[1]), "r"(a[2]), "r"(a[3]), "r"(b[0]), "r"(b[1]))

#define MMAS(d, a, b0, b1) \
  asm volatile("mma.sync.aligned.m16n8k16.row.col.f32.bf16.bf16.f32 " \
    "{%0,%1,%2,%3}, {%4,%5,%6,%7}, {%8,%9}, {%0,%1,%2,%3};" \
    : "+f"(d[0]), "+f"(d[1]), "+f"(d[2]), "+f"(d[3]) \
    : "r"(a[0]), "r"(a[1]), "r"(a[2]), "r"(a[3]), "r"(b0), "r"(b1))

// ---------------- small kernels ----------------
// rmsnorm: write fp32 (if outF) and/or bf16 hi/lo (if outH)
__global__ void rmsnorm_kernel(const float* __restrict__ x,
                               const float* __restrict__ scale,
                               float* __restrict__ outF,
                               __nv_bfloat16* __restrict__ outH,
                               __nv_bfloat16* __restrict__ outL) {
    int row = blockIdx.x;
    const float* xr = x + (long long)row * DD;
    __shared__ float red[256];
    float s = 0.f;
    for (int d = threadIdx.x; d < DD; d += 256) { float v = xr[d]; s += v * v; }
    red[threadIdx.x] = s; __syncthreads();
    for (int o = 128; o > 0; o >>= 1) {
        if (threadIdx.x < o) red[threadIdx.x] += red[threadIdx.x + o];
        __syncthreads();
    }
    float inv = 1.0f / sqrtf(red[0] / (float)DD + 1e-6f);
    for (int d = threadIdx.x; d < DD; d += 256) {
        float v = xr[d] * inv * scale[d];
        if (outF) outF[(long long)row * DD + d] = v;
        if (outH) {
            __nv_bfloat16 hb = __float2bfloat16(v);
            outH[(long long)row * DD + d] = hb;
            outL[(long long)row * DD + d] = __float2bfloat16(v - __bfloat162float(hb));
        }
    }
}

__global__ void rope_kernel(float* __restrict__ p, int H, long long total) {
    long long i = (long long)blockIdx.x * 256 + threadIdx.x;
    if (i >= total) return;
    int j = (int)(i & 31);
    long long nh = i >> 5;
    int h = (int)(nh % H);
    long long n = nh / H;
    int t = (int)(n % TT);
    float* v = p + (n * H + h) * KDn;
    float theta = powf(10000.0f, -(2.0f * j) / 64.0f);
    float a = (float)t * theta;
    float c = cosf(a), s = sinf(a);
    float x1 = v[j], x2 = v[j + 32];
    v[j]      = x1 * c - x2 * s;
    v[j + 32] = x2 * c + x1 * s;
}

__global__ void router_kernel(const float* __restrict__ rw, const float* __restrict__ rb) {
    int t = blockIdx.x;
    const float* xr = g_h2 + (long long)t * DD;
    float part[En];
    #pragma unroll
    for (int e = 0; e < En; e++) part[e] = 0.f;
    for (int d = threadIdx.x; d < DD; d += 256) {
        float xv = xr[d];
        #pragma unroll
        for (int e = 0; e < En; e++) part[e] += xv * rw[d * En + e];
    }
    __shared__ float red[En][8];
    int lane = threadIdx.x & 31, warp = threadIdx.x >> 5;
    #pragma unroll
    for (int e = 0; e < En; e++) {
        float v = part[e];
        for (int o = 16; o > 0; o >>= 1) v += __shfl_down_sync(0xffffffffu, v, o);
        if (lane == 0) red[e][warp] = v;
    }
    __syncthreads();
    if (threadIdx.x == 0) {
        float lg[En];
        #pragma unroll
        for (int e = 0; e < En; e++) {
            float s = 0.f;
            for (int w = 0; w < 8; w++) s += red[e][w];
            lg[e] = s + rb[e];
        }
        int i0 = 0;
        for (int e = 1; e < En; e++) if (lg[e] > lg[i0]) i0 = e;
        int i1 = -1;
        for (int e = 0; e < En; e++) {
            if (e == i0) continue;
            if (i1 < 0 || lg[e] > lg[i1]) i1 = e;
        }
        float e1 = expf(lg[i1] - lg[i0]);
        float denom = 1.f + e1;
        g_assign[2 * t] = i0;     g_assign[2 * t + 1] = i1;
        g_gate[2 * t] = 1.f / denom; g_gate[2 * t + 1] = e1 / denom;
    }
}

// parallel capacity scan: warp e handles expert e, ballot prefix over token order
__global__ void scan_kernel() {
    int lane = threadIdx.x & 31;
    int e = threadIdx.x >> 5;           // 8 warps = 8 experts
    uint32_t mle = 0xFFFFFFFFu >> (31 - lane);
    int base0 = 0, base1 = 0;
    for (int chunk = 0; chunk < NTOK / 32; chunk++) {
        int t = chunk * 32 + lane;
        int a0 = g_assign[2 * t], a1 = g_assign[2 * t + 1];
        uint32_t b0 = __ballot_sync(0xFFFFFFFFu, a0 == e);
        uint32_t b1 = __ballot_sync(0xFFFFFFFFu, a1 == e);
        int incl0 = __popc(b0 & mle);
        int incl1 = __popc(b1 & mle);
        if (a0 == e) {
            int p0 = base0 + incl0;
            g_slot[2 * t] = p0; g_keep[2 * t] = (p0 < CAPn) ? 1 : 0;
        }
        if (a1 == e) {
            int p1 = (base0 + incl0) + (base1 + incl1);
            g_slot[2 * t + 1] = p1; g_keep[2 * t + 1] = (p1 < CAPn) ? 1 : 0;
        }
        base0 += __popc(b0); base1 += __popc(b1);
    }
}

__global__ void zero_kernel(float* __restrict__ p, long long n) {
    long long i = (long long)blockIdx.x * 256 + threadIdx.x;
    if (i < n) p[i] = 0.f;
}

__global__ void scatter_kernel() {
    int i = blockIdx.x;
    if (!g_keep[i]) return;
    int t = i >> 1;
    int e = g_assign[i], s = g_slot[i];
    float* dst = g_grp + ((long long)e * CAPn + s) * DD;
    const float* src = g_h2 + (long long)t * DD;
    for (int d = threadIdx.x; d < DD; d += 256) atomicAdd(&dst[d], src[d]);
}

// gated gelu; writes bf16 hi/lo directly
__global__ void gelu_mul_kernel(__nv_bfloat16* __restrict__ oh,
                                __nv_bfloat16* __restrict__ ol, long long n) {
    long long i = (long long)blockIdx.x * 256 + threadIdx.x;
    if (i >= n) return;
    float x = g_t2[i] * g_t1[i];
    float x3 = x * x * x;
    float inner = 0.7978845608028654f * (x + 0.044715f * x3);
    float v = 0.5f * x * (1.0f + tanhf(inner));
    __nv_bfloat16 hb = __float2bfloat16(v);
    oh[i] = hb; ol[i] = __float2bfloat16(v - __bfloat162float(hb));
}

__global__ void combine_kernel(float* __restrict__ out) {
    int t = blockIdx.x;
    float gte0 = g_gate[2 * t], gte1 = g_gate[2 * t + 1];
    const float* s0 = g_keep[2 * t]
        ? g_eout + ((long long)g_assign[2 * t] * CAPn + g_slot[2 * t]) * DD
        : g_h2 + (long long)t * DD;
    const float* s1 = g_keep[2 * t + 1]
        ? g_eout + ((long long)g_assign[2 * t + 1] * CAPn + g_slot[2 * t + 1]) * DD
        : g_h2 + (long long)t * DD;
    const float* xr = g_x1 + (long long)t * DD;
    float* orow = out + (long long)t * DD;
    for (int d = threadIdx.x; d < DD; d += 256)
        orow[d] = xr[d] + gte0 * s0[d] + gte1 * s1[d];
}

__global__ void conv_kernel(const float* __restrict__ src, __nv_bfloat16* __restrict__ hi,
                            __nv_bfloat16* __restrict__ lo, long long n) {
    long long i = (long long)blockIdx.x * 256 + threadIdx.x;
    if (i >= n) return;
    float v = src[i];
    __nv_bfloat16 h = __float2bfloat16(v);
    hi[i] = h; lo[i] = __float2bfloat16(v - __bfloat162float(h));
}

__global__ void tconv_kernel(const float* __restrict__ src, __nv_bfloat16* __restrict__ hi,
                             __nv_bfloat16* __restrict__ lo, int R, int C, int lds,
                             long long so, long long si, int zdiv) {
    int z = blockIdx.z;
    src += (long long)(z / zdiv) * so + (long long)(z % zdiv) * si;
    long long d = (long long)z * R * C;
    hi += d; lo += d;
    __shared__ float t[32][33];
    int c0 = blockIdx.x * 32, r0 = blockIdx.y * 32;
    for (int i = threadIdx.y; i < 32; i += 8) {
        int r = r0 + i, c = c0 + threadIdx.x;
        if (r < R && c < C) t[i][threadIdx.x] = src[(long long)r * lds + c];
    }
    __syncthreads();
    for (int i = threadIdx.y; i < 32; i += 8) {
        int c = c0 + i, r = r0 + threadIdx.x;
        if (r < R && c < C) {
            float v = t[threadIdx.x][i];
            __nv_bfloat16 hh = __float2bfloat16(v);
            hi[(long long)c * R + r] = hh;
            lo[(long long)c * R + r] = __float2bfloat16(v - __bfloat162float(hh));
        }
    }
}

// ---------------- bf16 split-precision tensor-core GEMM (NT), 3-stage ----------------
#define TILEE (128*16)

__global__ void __launch_bounds__(256)
bgemm_kernel(int M, int N, int K,
             const __nv_bfloat16* __restrict__ Ah, const __nv_bfloat16* __restrict__ Al,
             int lda, long long soA, long long siA, int divA,
             const __nv_bfloat16* __restrict__ Bh, const __nv_bfloat16* __restrict__ Bl,
             int ldb, long long soB, long long siB, int divB,
             float* __restrict__ C, int ldc, long long soC, long long siC, int divC,
             int zdiv, int epi, const float* __restrict__ Rz) {
    int z = blockIdx.z;
    long long offA = (long long)(z / zdiv) * soA + (long long)((z % zdiv) / divA) * siA;
    long long offB = (long long)(z / zdiv) * soB + (long long)((z % zdiv) / divB) * siB;
    long long offC = (long long)(z / zdiv) * soC + (long long)((z % zdiv) / divC) * siC;
    Ah += offA; Al += offA; Bh += offB; Bl += offB; C += offC;
    const float* Rp = Rz ? (Rz + offC) : (const float*)0;

    int m0 = blockIdx.y * 128, n0 = blockIdx.x * 128;
    int tid = threadIdx.x;

    __shared__ __nv_bfloat16 sm[3][4][TILEE];   // 48KB
    uint32_t sbase = (uint32_t)__cvta_generic_to_shared(&sm[0][0][0]);

    int lr = tid >> 1, lc = tid & 1;
    const __nv_bfloat16* gAh = Ah + (long long)(m0 + lr) * lda + lc * 8;
    const __nv_bfloat16* gAl = Al + (long long)(m0 + lr) * lda + lc * 8;
    int brow = n0 + lr;
    int bvalid = (brow < N) ? 1 : 0;
    const __nv_bfloat16* gBh = Bh + (long long)(bvalid ? brow : 0) * ldb + lc * 8;
    const __nv_bfloat16* gBl = Bl + (long long)(bvalid ? brow : 0) * ldb + lc * 8;
    unsigned bsz = bvalid ? 16u : 0u;
    uint32_t soff = (uint32_t)swz(lr, lc * 8) * 2;

    int KT = K / 16;

    auto prefetch = [&](int kt, int st) {
        long long ko = (long long)kt * 16;
        uint32_t b0 = sbase + (uint32_t)(st * 4 * TILEE * 2);
        asm volatile("cp.async.cg.shared.global [%0], [%1], 16;"
                     :: "r"(b0 + soff), "l"(gAh + ko));
        asm volatile("cp.async.cg.shared.global [%0], [%1], 16;"
                     :: "r"(b0 + (uint32_t)(TILEE * 2) + soff), "l"(gAl + ko));
        asm volatile("cp.async.cg.shared.global [%0], [%1], 16, %2;"
                     :: "r"(b0 + (uint32_t)(2 * TILEE * 2) + soff), "l"(gBh + ko), "r"(bsz));
        asm volatile("cp.async.cg.shared.global [%0], [%1], 16, %2;"
                     :: "r"(b0 + (uint32_t)(3 * TILEE * 2) + soff), "l"(gBl + ko), "r"(bsz));
    };

    float acc[4][4][4];
    #pragma unroll
    for (int i = 0; i < 4; i++)
        #pragma unroll
        for (int j = 0; j < 4; j++)
            #pragma unroll
            for (int e = 0; e < 4; e++) acc[i][j][e] = 0.f;

    int lane = tid & 31, wid = tid >> 5;
    int wm = wid & 1, wn = wid >> 1;
    int arow = wm * 64 + (lane & 15);
    int ak = (lane >> 4) * 8;
    int brow2 = wn * 32 + (lane & 7) + ((lane & 16) ? 8 : 0);
    int bk = (lane & 8) ? 8 : 0;

    prefetch(0, 0);
    asm volatile("cp.async.commit_group;");
    if (KT > 1) { prefetch(1, 1); asm volatile("cp.async.commit_group;"); }

    for (int kt = 0; kt < KT; kt++) {
        if (kt + 2 < KT) {
            prefetch(kt + 2, (kt + 2) % 3);
            asm volatile("cp.async.commit_group;");
            asm volatile("cp.async.wait_group 2;");
        } else if (kt + 1 < KT) {
            asm volatile("cp.async.wait_group 1;");
        } else {
            asm volatile("cp.async.wait_group 0;");
        }
        __syncthreads();

        uint32_t base = sbase + (uint32_t)((kt % 3) * 4 * TILEE * 2);
        uint32_t fAh[4][4], fAl[4][4], fBh[4][2], fBl[4][2];
        #pragma unroll
        for (int mi = 0; mi < 4; mi++) {
            uint32_t ao = base + (uint32_t)swz(arow + mi * 16, ak) * 2;
            LDSM4(fAh[mi][0], fAh[mi][1], fAh[mi][2], fAh[mi][3], ao);
            LDSM4(fAl[mi][0], fAl[mi][1], fAl[mi][2], fAl[mi][3], ao + (uint32_t)(TILEE * 2));
        }
        #pragma unroll
        for (int nj = 0; nj < 2; nj++) {
            uint32_t bo = base + (uint32_t)(2 * TILEE * 2) + (uint32_t)swz(brow2 + nj * 16, bk) * 2;
            uint32_t r0, r1, r2, r3;
            LDSM4(r0, r1, r2, r3, bo);
            fBh[nj * 2][0] = r0; fBh[nj * 2][1] = r1;
            fBh[nj * 2 + 1][0] = r2; fBh[nj * 2 + 1][1] = r3;
            LDSM4(r0, r1, r2, r3, bo + (uint32_t)(TILEE * 2));
            fBl[nj * 2][0] = r0; fBl[nj * 2][1] = r1;
            fBl[nj * 2 + 1][0] = r2; fBl[nj * 2 + 1][1] = r3;
        }
        #pragma unroll
        for (int mi = 0; mi < 4; mi++)
            #pragma unroll
            for (int ni = 0; ni < 4; ni++) {
                MMA16816(acc[mi][ni], fAh[mi], fBh[ni]);
                MMA16816(acc[mi][ni], fAh[mi], fBl[ni]);
                MMA16816(acc[mi][ni], fAl[mi], fBh[ni]);
            }
        __syncthreads();
    }

    int r4 = lane >> 2, c2 = (lane & 3) * 2;
    #pragma unroll
    for (int mi = 0; mi < 4; mi++)
        #pragma unroll
        for (int ni = 0; ni < 4; ni++) {
            int row = m0 + wm * 64 + mi * 16 + r4;
            int col = n0 + wn * 32 + ni * 8 + c2;
            #pragma unroll
            for (int e = 0; e < 4; e++) {
                int rr = row + (e >> 1) * 8;
                int cc = col + (e & 1);
                if (cc < N) {
                    float v = acc[mi][ni][e];
                    if (epi == 2) v += Rp[(long long)rr * ldc + cc];
                    C[(long long)rr * ldc + cc] = v;
                }
            }
        }
}

// ---------------- fused flash attention ----------------
// grid (8 qblocks, 32 b*h); 256 threads; 96KB dyn smem.
// reads bq/bk (hi/lo, [tok][heads][64]) and bvt (hi/lo, [b][hk][vd][tok]);
// writes batt hi/lo ([tok][1024]).
__global__ void __launch_bounds__(256, 1)
flash_kernel(const __nv_bfloat16* __restrict__ bq,
             const __nv_bfloat16* __restrict__ bk,
             const __nv_bfloat16* __restrict__ bvt,
             __nv_bfloat16* __restrict__ batt) {
    extern __shared__ __nv_bfloat16 smf[];
    __nv_bfloat16 *qh = smf,          *ql = smf + 8192;
    __nv_bfloat16 *kh = smf + 16384,  *kl = smf + 24576;
    __nv_bfloat16 *vh = smf + 32768,  *vl = smf + 40960;

    int tid = threadIdx.x, lane = tid & 31, w = tid >> 5;
    int qb = blockIdx.x, bhid = blockIdx.y;
    int b = bhid >> 4, h = bhid & 15, hk = h >> 2;

    const __nv_bfloat16 *gqh = bq,  *gql = bq + SZ_Q;
    const __nv_bfloat16 *gkh = bk,  *gkl = bk + SZ_K;
    const __nv_bfloat16 *gvh = bvt, *gvl = bvt + SZ_VT;

    // load Q tile (128x64) hi/lo, swizzled in 16-wide chunks
    for (int idx = tid; idx < 2048; idx += 256) {
        int row = idx >> 4, c4 = (idx & 15) * 4;
        long long ga = ((long long)((b * 1024 + qb * 128 + row) * 16 + h)) * 64 + c4;
        int sa = (c4 >> 4) * 2048 + swz(row, c4 & 15);
        *(uint2*)&qh[sa] = *(const uint2*)&gqh[ga];
        *(uint2*)&ql[sa] = *(const uint2*)&gql[ga];
    }

    uint32_t qbase  = (uint32_t)__cvta_generic_to_shared(qh);
    uint32_t qlbase = (uint32_t)__cvta_generic_to_shared(ql);
    uint32_t kbase  = (uint32_t)__cvta_generic_to_shared(kh);
    uint32_t klbase = (uint32_t)__cvta_generic_to_shared(kl);
    uint32_t vbase  = (uint32_t)__cvta_generic_to_shared(vh);
    uint32_t vlbase = (uint32_t)__cvta_generic_to_shared(vl);

    float oAcc[8][4];
    #pragma unroll
    for (int i = 0; i < 8; i++)
        #pragma unroll
        for (int e = 0; e < 4; e++) oAcc[i][e] = 0.f;
    float m_prev[2] = {-1e30f, -1e30f};
    float l_run[2] = {0.f, 0.f};

    int arow = w * 16 + (lane & 15), akk = (lane >> 4) * 8;
    int brow = (lane & 7) + ((lane & 16) ? 8 : 0);
    int bko = (lane & 8) ? 8 : 0;
    int r4 = lane >> 2, c2 = (lane & 3) * 2;

    for (int kb = 0; kb <= qb; kb++) {
        __syncthreads();
        // load K tile (128 tok x 64) hi/lo
        for (int idx = tid; idx < 2048; idx += 256) {
            int row = idx >> 4, c4 = (idx & 15) * 4;
            long long ga = ((long long)((b * 1024 + kb * 128 + row) * 4 + hk)) * 64 + c4;
            int sa = (c4 >> 4) * 2048 + swz(row, c4 & 15);
            *(uint2*)&kh[sa] = *(const uint2*)&gkh[ga];
            *(uint2*)&kl[sa] = *(const uint2*)&gkl[ga];
        }
        // load V^T tile (64 vd x 128 tok) hi/lo
        for (int idx = tid; idx < 2048; idx += 256) {
            int vd = idx >> 5, t4 = (idx & 31) * 4;
            long long ga = ((long long)((b * 4 + hk) * 64 + vd)) * 1024 + kb * 128 + t4;
            int sa = (t4 >> 4) * 1024 + swz(vd, t4 & 15);
            *(uint2*)&vh[sa] = *(const uint2*)&gvh[ga];
            *(uint2*)&vl[sa] = *(const uint2*)&gvl[ga];
        }
        __syncthreads();

        // ---- S = Q K^T (3-pass hi/lo) ----
        float sAcc[16][4];
        #pragma unroll
        for (int t = 0; t < 16; t++)
            #pragma unroll
            for (int e = 0; e < 4; e++) sAcc[t][e] = 0.f;

        #pragma unroll
        for (int kk = 0; kk < 4; kk++) {
            uint32_t aH[4], aL[4];
            uint32_t qa = qbase + (uint32_t)(kk * 2048 + swz(arow, akk)) * 2;
            LDSM4(aH[0], aH[1], aH[2], aH[3], qa);
            uint32_t qla = qlbase + (uint32_t)(kk * 2048 + swz(arow, akk)) * 2;
            LDSM4(aL[0], aL[1], aL[2], aL[3], qla);
            #pragma unroll
            for (int nb = 0; nb < 8; nb++) {
                uint32_t off = (uint32_t)(kk * 2048 + swz(nb * 16 + brow, bko)) * 2;
                uint32_t r0, r1, r2, r3, s0, s1, s2, s3;
                LDSM4(r0, r1, r2, r3, kbase + off);
                LDSM4(s0, s1, s2, s3, klbase + off);
                MMAS(sAcc[2 * nb],     aH, r0, r1);
                MMAS(sAcc[2 * nb],     aH, s0, s1);
                MMAS(sAcc[2 * nb],     aL, r0, r1);
                MMAS(sAcc[2 * nb + 1], aH, r2, r3);
                MMAS(sAcc[2 * nb + 1], aH, s2, s3);
                MMAS(sAcc[2 * nb + 1], aL, r2, r3);
            }
        }

        // scale + causal mask (diag block)
        #pragma unroll
        for (int t = 0; t < 16; t++)
            #pragma unroll
            for (int e = 0; e < 4; e++) {
                float v = sAcc[t][e] * 0.125f;
                if (kb == qb) {
                    int col = t * 8 + c2 + (e & 1);
                    int rowl = w * 16 + r4 + ((e >> 1) ? 8 : 0);
                    if (col > rowl) v = -1e30f;
                }
                sAcc[t][e] = v;
            }

        // online softmax (rows owned by quads)
        float m0 = -1e30f, m1 = -1e30f;
        #pragma unroll
        for (int t = 0; t < 16; t++) {
            m0 = fmaxf(m0, fmaxf(sAcc[t][0], sAcc[t][1]));
            m1 = fmaxf(m1, fmaxf(sAcc[t][2], sAcc[t][3]));
        }
        m0 = fmaxf(m0, __shfl_xor_sync(0xFFFFFFFFu, m0, 1));
        m0 = fmaxf(m0, __shfl_xor_sync(0xFFFFFFFFu, m0, 2));
        m1 = fmaxf(m1, __shfl_xor_sync(0xFFFFFFFFu, m1, 1));
        m1 = fmaxf(m1, __shfl_xor_sync(0xFFFFFFFFu, m1, 2));
        float mn0 = fmaxf(m_prev[0], m0), mn1 = fmaxf(m_prev[1], m1);
        float al0 = __expf(m_prev[0] - mn0), al1 = __expf(m_prev[1] - mn1);
        float rs0 = 0.f, rs1 = 0.f;
        #pragma unroll
        for (int t = 0; t < 16; t++) {
            sAcc[t][0] = __expf(sAcc[t][0] - mn0);
            sAcc[t][1] = __expf(sAcc[t][1] - mn0);
            sAcc[t][2] = __expf(sAcc[t][2] - mn1);
            sAcc[t][3] = __expf(sAcc[t][3] - mn1);
            rs0 += sAcc[t][0] + sAcc[t][1];
            rs1 += sAcc[t][2] + sAcc[t][3];
        }
        rs0 += __shfl_xor_sync(0xFFFFFFFFu, rs0, 1);
        rs0 += __shfl_xor_sync(0xFFFFFFFFu, rs0, 2);
        rs1 += __shfl_xor_sync(0xFFFFFFFFu, rs1, 1);
        rs1 += __shfl_xor_sync(0xFFFFFFFFu, rs1, 2);
        l_run[0] = l_run[0] * al0 + rs0;
        l_run[1] = l_run[1] * al1 + rs1;
        m_prev[0] = mn0; m_prev[1] = mn1;
        #pragma unroll
        for (int ot = 0; ot < 8; ot++) {
            oAcc[ot][0] *= al0; oAcc[ot][1] *= al0;
            oAcc[ot][2] *= al1; oAcc[ot][3] *= al1;
        }

        // ---- O += P V (3-pass hi/lo; P fragments from accumulators) ----
        #pragma unroll
        for (int kk = 0; kk < 8; kk++) {
            float* sA = sAcc[2 * kk];
            float* sB = sAcc[2 * kk + 1];
            uint32_t aH[4], aL[4];
            aH[0] = pack2(sA[0], sA[1]); aH[1] = pack2(sA[2], sA[3]);
            aH[2] = pack2(sB[0], sB[1]); aH[3] = pack2(sB[2], sB[3]);
            aL[0] = pack2(lopart(sA[0]), lopart(sA[1]));
            aL[1] = pack2(lopart(sA[2]), lopart(sA[3]));
            aL[2] = pack2(lopart(sB[0]), lopart(sB[1]));
            aL[3] = pack2(lopart(sB[2]), lopart(sB[3]));
            #pragma unroll
            for (int vb = 0; vb < 4; vb++) {
                uint32_t off = (uint32_t)(kk * 1024 + swz(vb * 16 + brow, bko)) * 2;
                uint32_t r0, r1, r2, r3, s0, s1, s2, s3;
                LDSM4(r0, r1, r2, r3, vbase + off);
                LDSM4(s0, s1, s2, s3, vlbase + off);
                MMAS(oAcc[2 * vb],     aH, r0, r1);
                MMAS(oAcc[2 * vb],     aH, s0, s1);
                MMAS(oAcc[2 * vb],     aL, r0, r1);
                MMAS(oAcc[2 * vb + 1], aH, r2, r3);
                MMAS(oAcc[2 * vb + 1], aH, s2, s3);
                MMAS(oAcc[2 * vb + 1], aL, r2, r3);
            }
        }
    }

    // epilogue: normalize, write batt hi/lo
    float inv0 = 1.f / l_run[0], inv1 = 1.f / l_run[1];
    __nv_bfloat16 *oh = batt, *ol = batt + SZ_ATT;
    #pragma unroll
    for (int ot = 0; ot < 8; ot++)
        #pragma unroll
        for (int e = 0; e < 4; e++) {
            float v = oAcc[ot][e] * ((e >> 1) ? inv1 : inv0);
            int rowl = w * 16 + r4 + ((e >> 1) ? 8 : 0);
            long long oi = ((long long)(b * 1024 + qb * 128 + rowl)) * 1024
                           + h * 64 + ot * 8 + c2 + (e & 1);
            __nv_bfloat16 hb = __float2bfloat16(v);
            oh[oi] = hb;
            ol[oi] = __float2bfloat16(v - __bfloat162float(hb));
        }
}

// ---------------- launch ----------------
extern "C" void kernel_launch(void* const* d_in, const int* in_sizes, int n_in,
                              void* d_out, int out_size) {
    const float* x   = (const float*)d_in[0];
    const float* wq  = (const float*)d_in[1];
    const float* wk  = (const float*)d_in[2];
    const float* wv  = (const float*)d_in[3];
    const float* wo  = (const float*)d_in[4];
    const float* rw  = (const float*)d_in[5];
    const float* rb  = (const float*)d_in[6];
    const float* w1  = (const float*)d_in[7];
    const float* w2  = (const float*)d_in[8];
    const float* w3  = (const float*)d_in[9];
    const float* ns1 = (const float*)d_in[10];
    const float* ns2 = (const float*)d_in[11];

    float *q, *k, *v, *x1, *h2, *grp, *t1, *t2, *eout;
    cudaGetSymbolAddress((void**)&q, g_q);
    cudaGetSymbolAddress((void**)&k, g_k);
    cudaGetSymbolAddress((void**)&v, g_v);
    cudaGetSymbolAddress((void**)&x1, g_x1);
    cudaGetSymbolAddress((void**)&h2, g_h2);
    cudaGetSymbolAddress((void**)&grp, g_grp);
    cudaGetSymbolAddress((void**)&t1, g_t1);
    cudaGetSymbolAddress((void**)&t2, g_t2);
    cudaGetSymbolAddress((void**)&eout, g_eout);

    __nv_bfloat16 *bh, *bq, *bk, *bvt, *batt, *bgrp, *bt1;
    __nv_bfloat16 *wqT, *wkT, *wvT, *woT, *w1T, *w2T, *w3T;
    cudaGetSymbolAddress((void**)&bh, b_h);
    cudaGetSymbolAddress((void**)&bq, b_q);
    cudaGetSymbolAddress((void**)&bk, b_k);
    cudaGetSymbolAddress((void**)&bvt, b_vt);
    cudaGetSymbolAddress((void**)&batt, b_attn);
    cudaGetSymbolAddress((void**)&bgrp, b_grp);
    cudaGetSymbolAddress((void**)&bt1, b_t1);
    cudaGetSymbolAddress((void**)&wqT, b_wqT);
    cudaGetSymbolAddress((void**)&wkT, b_wkT);
    cudaGetSymbolAddress((void**)&wvT, b_wvT);
    cudaGetSymbolAddress((void**)&woT, b_woT);
    cudaGetSymbolAddress((void**)&w1T, b_w1T);
    cudaGetSymbolAddress((void**)&w2T, b_w2T);
    cudaGetSymbolAddress((void**)&w3T, b_w3T);

    auto conv = [&](const float* s, __nv_bfloat16* d, long long size) {
        conv_kernel<<<(unsigned)((size + 255) / 256), 256>>>(s, d, d + size, size);
    };
    auto tconv = [&](const float* s, __nv_bfloat16* d, long long size,
                     int R, int C, int lds, long long so, long long si, int zdiv, int Z) {
        dim3 grid((C + 31) / 32, (R + 31) / 32, Z);
        tconv_kernel<<<grid, dim3(32, 8)>>>(s, d, d + size, R, C, lds, so, si, zdiv);
    };
    auto bgemm = [&](int M, int N, int K,
                     const __nv_bfloat16* A, long long szA, int lda, long long soA, long long siA, int divA,
                     const __nv_bfloat16* B, long long szB, int ldb, long long soB, long long siB, int divB,
                     float* C, int ldc, long long soC, long long siC, int divC,
                     int Z, int zdiv, int epi, const float* R) {
        dim3 grid((N + 127) / 128, M / 128, Z);
        bgemm_kernel<<<grid, 256>>>(M, N, K,
                                    A, A + szA, lda, soA, siA, divA,
                                    B, B + szB, ldb, soB, siB, divB,
                                    C, ldc, soC, siC, divC,
                                    zdiv, epi, R);
    };

    // weight transposes + conversions (NT layout: N x K)
    tconv(wq, wqT, SZ_WQT, 1024, 1024, 1024, 0, 0, 1, 1);
    tconv(wk, wkT, SZ_WKT, 1024, 256, 256, 0, 0, 1, 1);
    tconv(wv, wvT, SZ_WKT, 1024, 256, 256, 0, 0, 1, 1);
    tconv(wo, woT, SZ_WOT, 1024, 1024, 1024, 0, 0, 1, 1);
    tconv(w1, w1T, SZ_W1T, 1024, 2048, 2048, (long long)DD * HIDn, 0, 1, En);
    tconv(w2, w2T, SZ_W1T, 1024, 2048, 2048, (long long)DD * HIDn, 0, 1, En);
    tconv(w3, w3T, SZ_W3T, 2048, 1024, 1024, (long long)HIDn * DD, 0, 1, En);

    // ---- attention ----
    rmsnorm_kernel<<<NTOK, 256>>>(x, ns1, nullptr, bh, bh + SZ_H);
    bgemm(NTOK, 1024, 1024, bh, SZ_H, 1024, 0, 0, 1, wqT, SZ_WQT, 1024, 0, 0, 1,
          q, 1024, 0, 0, 1, 1, 1, 0, nullptr);
    bgemm(NTOK, 256, 1024, bh, SZ_H, 1024, 0, 0, 1, wkT, SZ_WKT, 1024, 0, 0, 1,
          k, 256, 0, 0, 1, 1, 1, 0, nullptr);
    bgemm(NTOK, 256, 1024, bh, SZ_H, 1024, 0, 0, 1, wvT, SZ_WKT, 1024, 0, 0, 1,
          v, 256, 0, 0, 1, 1, 1, 0, nullptr);
    {
        long long tq = (long long)NTOK * HQn * 32;
        rope_kernel<<<(unsigned)((tq + 255) / 256), 256>>>(q, HQn, tq);
        long long tk = (long long)NTOK * HKVn * 32;
        rope_kernel<<<(unsigned)((tk + 255) / 256), 256>>>(k, HKVn, tk);
    }
    conv(q, bq, SZ_Q);
    conv(k, bk, SZ_K);
    tconv(v, bvt, SZ_VT, TT, VDn, HKVn * VDn, (long long)TT * HKVn * VDn, VDn, HKVn, BB * HKVn);

    cudaFuncSetAttribute(flash_kernel, cudaFuncAttributeMaxDynamicSharedMemorySize, 98304);
    flash_kernel<<<dim3(8, 32), 256, 98304>>>(bq, bk, bvt, batt);

    // x1 = x + attn @ wo
    bgemm(NTOK, 1024, 1024, batt, SZ_ATT, 1024, 0, 0, 1, woT, SZ_WOT, 1024, 0, 0, 1,
          x1, 1024, 0, 0, 1, 1, 1, 2, x);

    // ---- MoE ----
    rmsnorm_kernel<<<NTOK, 256>>>(x1, ns2, h2, nullptr, nullptr);
    router_kernel<<<NTOK, 256>>>(rw, rb);
    scan_kernel<<<1, 256>>>();
    {
        long long n = (long long)En * CAPn * DD;
        zero_kernel<<<(unsigned)((n + 255) / 256), 256>>>(grp, n);
    }
    scatter_kernel<<<NTOK * 2, 256>>>();
    conv(grp, bgrp, SZ_GRP);
    bgemm(CAPn, HIDn, DD,
          bgrp, SZ_GRP, 1024, (long long)CAPn * DD, 0, 1,
          w1T, SZ_W1T, 1024, (long long)HIDn * DD, 0, 1,
          t1, HIDn, (long long)CAPn * HIDn, 0, 1,
          En, 1, 0, nullptr);
    bgemm(CAPn, HIDn, DD,
          bgrp, SZ_GRP, 1024, (long long)CAPn * DD, 0, 1,
          w2T, SZ_W1T, 1024, (long long)HIDn * DD, 0, 1,
          t2, HIDn, (long long)CAPn * HIDn, 0, 1,
          En, 1, 0, nullptr);
    {
        long long n = (long long)En * CAPn * HIDn;
        gelu_mul_kernel<<<(unsigned)((n + 255) / 256), 256>>>(bt1, bt1 + SZ_T1, n);
    }
    bgemm(CAPn, DD, HIDn,
          bt1, SZ_T1, HIDn, (long long)CAPn * HIDn, 0, 1,
          w3T, SZ_W3T, 2048, (long long)DD * HIDn, 0, 1,
          eout, DD, (long long)CAPn * DD, 0, 1,
          En, 1, 0, nullptr);
    combine_kernel<<<NTOK, 256>>>((float*)d_out);
}